// round 7
// baseline (speedup 1.0000x reference)
#include <cuda_runtime.h>

#define NN 100000
#define NE 600000
#define DI 128
#define DH 128
#define NC 64

// Scratch (device globals -- referenced ONLY inside kernels, never from host)
__device__ __align__(16) float g_nbr1[(size_t)NN * DI];   // layer-1 neighbor sums (128-wide)
__device__ __align__(16) float g_h1[(size_t)NN * DH];     // layer-1 activations
__device__ __align__(16) float g_p[(size_t)NN * NC];      // h1 @ Wn2 (pre-projected, 64-wide)
__device__ __align__(16) float g_nbr2[(size_t)NN * NC];   // layer-2 neighbor sums (64-wide)
__device__ float g_deg[NN];                               // in-degree (float)

// ---------------- packed f32x2 helpers (sm_103a FFMA2) ----------------
__device__ __forceinline__ unsigned long long dup2(float x) {
    unsigned long long r;
    asm("mov.b64 %0, {%1, %1};" : "=l"(r) : "f"(x));
    return r;
}
__device__ __forceinline__ void ffma2(unsigned long long& d,
                                      unsigned long long a, unsigned long long b) {
    asm("fma.rn.f32x2 %0, %1, %2, %0;" : "+l"(d) : "l"(a), "l"(b));
}
__device__ __forceinline__ float2 unpk(unsigned long long v) {
    float2 f;
    asm("mov.b64 {%0, %1}, %2;" : "=f"(f.x), "=f"(f.y) : "l"(v));
    return f;
}

// ---------------------------------------------------------------------------
__global__ void zero_kernel() {
    const int n1 = NN * DI / 4;
    const int n2 = NN * NC / 4;
    const int nd = NN / 4;
    int i = blockIdx.x * blockDim.x + threadIdx.x;
    float4 z = make_float4(0.f, 0.f, 0.f, 0.f);
    if (i < n1)                 ((float4*)g_nbr1)[i] = z;
    else if (i < n1 + n2)       ((float4*)g_nbr2)[i - n1] = z;
    else if (i < n1 + n2 + nd)  ((float4*)g_deg)[i - n1 - n2] = z;
}

// ---------------------------------------------------------------------------
// Layer-1 edge scatter: warp per edge, 128 floats as 32 x float4 REDG, + degree
// ---------------------------------------------------------------------------
__global__ void scatter1_kernel(const float* __restrict__ x,
                                const int* __restrict__ src,
                                const int* __restrict__ dst) {
    int gw = (blockIdx.x * blockDim.x + threadIdx.x) >> 5;
    if (gw >= NE) return;
    int lane = threadIdx.x & 31;
    int s = __ldg(src + gw);
    int d = __ldg(dst + gw);
    float4 v = ((const float4*)x)[(size_t)s * 32 + lane];
    float4* p = ((float4*)g_nbr1) + (size_t)d * 32 + lane;
    asm volatile("red.global.add.v4.f32 [%0], {%1, %2, %3, %4};"
                 :: "l"(p), "f"(v.x), "f"(v.y), "f"(v.z), "f"(v.w)
                 : "memory");
    if (lane == 0) atomicAdd(&g_deg[d], 1.0f);
}

// ---------------------------------------------------------------------------
// Layer-2 edge scatter of pre-projected g_p (64-wide): HALF-warp per edge.
// ---------------------------------------------------------------------------
__global__ void scatter2_kernel(const int* __restrict__ src,
                                const int* __restrict__ dst) {
    int gw = (blockIdx.x * blockDim.x + threadIdx.x) >> 5;
    int lane = threadIdx.x & 31;
    int e = gw * 2 + (lane >> 4);
    if (e >= NE) return;
    int l16 = lane & 15;
    int s = __ldg(src + e);
    int d = __ldg(dst + e);
    float4 v = ((const float4*)g_p)[(size_t)s * 16 + l16];
    float4* p = ((float4*)g_nbr2) + (size_t)d * 16 + l16;
    asm volatile("red.global.add.v4.f32 [%0], {%1, %2, %3, %4};"
                 :: "l"(p), "f"(v.x), "f"(v.y), "f"(v.z), "f"(v.w)
                 : "memory");
}

// ---------------------------------------------------------------------------
// Layer 1: h1 = relu(x @ Wself + (nbr1/max(deg,1)) @ Wneigh + b1)
// M-tile 128, N=128, K=2x128 phases. 256 threads, 8M(4 pairs)x8N per thread.
// 32 FFMA2 per k-iter. SMEM: Ws 64K + Wn 64K + As 64K = 192KB (1 CTA/SM).
// ---------------------------------------------------------------------------
__global__ void __launch_bounds__(256)
gemm1_kernel(const float* __restrict__ x,
             const float* __restrict__ Ws_g,
             const float* __restrict__ Wn_g,
             const float* __restrict__ bias) {
    extern __shared__ float sm[];
    float* Ws = sm;                 // [128][128]
    float* Wn = sm + DI * DH;       // [128][128]
    float* As = sm + 2 * DI * DH;   // [128 k][128 m]

    int tid = threadIdx.x;
    {
        const float4* s4 = (const float4*)Ws_g;
        const float4* n4 = (const float4*)Wn_g;
        float4* ws4 = (float4*)Ws;
        float4* wn4 = (float4*)Wn;
        for (int i = tid; i < DI * DH / 4; i += 256) { ws4[i] = s4[i]; wn4[i] = n4[i]; }
    }
    int ty = tid >> 4;              // rows ty*8 .. +7 (4 pairs)
    int tx = tid & 15;              // cols tx*8 .. +7
    float bb[8];
    #pragma unroll
    for (int j = 0; j < 8; j++) bb[j] = __ldg(bias + (tx << 3) + j);

    int m_ld = tid >> 1;            // node-row this thread loads
    int c0 = (tid & 1) * 64;        // feature half

    const int nTiles = (NN + 127) / 128;
    for (int tile = blockIdx.x; tile < nTiles; tile += gridDim.x) {
        int base = tile * 128;
        unsigned long long acc[4][8];
        #pragma unroll
        for (int pr = 0; pr < 4; pr++)
            #pragma unroll
            for (int j = 0; j < 8; j++) acc[pr][j] = 0ull;

        #pragma unroll
        for (int ph = 0; ph < 2; ++ph) {
            __syncthreads();
            {   // A-tile load: 128 nodes x 128 feats, K-major transposed
                const float* feat = ph ? g_nbr1 : x;
                int node = base + m_ld;
                bool valid = node < NN;
                float scale = 1.0f;
                if (ph && valid) scale = 1.0f / fmaxf(g_deg[node], 1.0f);
                const float4* row = (const float4*)(feat + (size_t)node * DI);
                #pragma unroll
                for (int i = 0; i < 16; i++) {
                    int c = c0 + i * 4;
                    float4 v = make_float4(0.f, 0.f, 0.f, 0.f);
                    if (valid) v = row[c >> 2];
                    As[(c + 0) * 128 + m_ld] = v.x * scale;
                    As[(c + 1) * 128 + m_ld] = v.y * scale;
                    As[(c + 2) * 128 + m_ld] = v.z * scale;
                    As[(c + 3) * 128 + m_ld] = v.w * scale;
                }
            }
            __syncthreads();
            const float* W = ph ? Wn : Ws;
            #pragma unroll 2
            for (int k = 0; k < 128; ++k) {
                ulonglong2 a0 = *(const ulonglong2*)(As + k * 128 + (ty << 3));
                ulonglong2 a1 = *(const ulonglong2*)(As + k * 128 + (ty << 3) + 4);
                float4 b0 = *(const float4*)(W + k * DH + (tx << 3));
                float4 b1 = *(const float4*)(W + k * DH + (tx << 3) + 4);
                unsigned long long ap[4] = {a0.x, a0.y, a1.x, a1.y};
                unsigned long long bd[8] = {dup2(b0.x), dup2(b0.y), dup2(b0.z), dup2(b0.w),
                                            dup2(b1.x), dup2(b1.y), dup2(b1.z), dup2(b1.w)};
                #pragma unroll
                for (int pr = 0; pr < 4; pr++)
                    #pragma unroll
                    for (int j = 0; j < 8; j++)
                        ffma2(acc[pr][j], ap[pr], bd[j]);
            }
        }
        // epilogue: bias + relu -> g_h1
        #pragma unroll
        for (int pr = 0; pr < 4; pr++) {
            float2 v[8];
            #pragma unroll
            for (int j = 0; j < 8; j++) v[j] = unpk(acc[pr][j]);
            #pragma unroll
            for (int half = 0; half < 2; half++) {
                int r = base + (ty << 3) + pr * 2 + half;
                if (r < NN) {
                    float* o = g_h1 + (size_t)r * DH + (tx << 3);
                    float e0 = half ? v[0].y : v[0].x;
                    float e1 = half ? v[1].y : v[1].x;
                    float e2 = half ? v[2].y : v[2].x;
                    float e3 = half ? v[3].y : v[3].x;
                    float e4 = half ? v[4].y : v[4].x;
                    float e5 = half ? v[5].y : v[5].x;
                    float e6 = half ? v[6].y : v[6].x;
                    float e7 = half ? v[7].y : v[7].x;
                    float4 o0, o1;
                    o0.x = fmaxf(e0 + bb[0], 0.f); o0.y = fmaxf(e1 + bb[1], 0.f);
                    o0.z = fmaxf(e2 + bb[2], 0.f); o0.w = fmaxf(e3 + bb[3], 0.f);
                    o1.x = fmaxf(e4 + bb[4], 0.f); o1.y = fmaxf(e5 + bb[5], 0.f);
                    o1.z = fmaxf(e6 + bb[6], 0.f); o1.w = fmaxf(e7 + bb[7], 0.f);
                    *(float4*)o = o0; *(float4*)(o + 4) = o1;
                }
            }
        }
    }
}

// ---------------------------------------------------------------------------
// Fused N=64 dual-GEMM: one pass over A = g_h1 computes BOTH
//   d_out (self part + bias)  = h1 @ Ws2 + b2       (nbr2/deg added later)
//   g_p   (neighbor proj)     = h1 @ Wn2
// M-tile 128, 256 threads, 8M(4 pairs) x 4N x 2 matrices = 32 FFMA2/k.
// SMEM: Ws 32K + Wn 32K + As 64K = 128KB (1 CTA/SM).
// ---------------------------------------------------------------------------
__global__ void __launch_bounds__(256)
gemm64f_kernel(const float* __restrict__ Ws_g,
               const float* __restrict__ Wn_g,
               const float* __restrict__ bias,
               float* __restrict__ out_ext) {
    extern __shared__ float sm[];
    float* Ws = sm;                 // [128][64]
    float* Wn = sm + DH * NC;       // [128][64]
    float* As = sm + 2 * DH * NC;   // [128 k][128 m]

    const float* A = g_h1;

    int tid = threadIdx.x;
    {
        const float4* s4 = (const float4*)Ws_g;
        const float4* n4 = (const float4*)Wn_g;
        float4* ws4 = (float4*)Ws;
        float4* wn4 = (float4*)Wn;
        for (int i = tid; i < DH * NC / 4; i += 256) { ws4[i] = s4[i]; wn4[i] = n4[i]; }
    }
    int ty = tid >> 4;              // rows ty*8 (4 pairs)
    int tx = tid & 15;              // cols tx*4
    float4 bb = *(const float4*)(bias + (tx << 2));

    int m_ld = tid >> 1;
    int c0 = (tid & 1) * 64;

    const int nTiles = (NN + 127) / 128;
    for (int tile = blockIdx.x; tile < nTiles; tile += gridDim.x) {
        int base = tile * 128;
        unsigned long long accS[4][4], accN[4][4];
        #pragma unroll
        for (int pr = 0; pr < 4; pr++)
            #pragma unroll
            for (int j = 0; j < 4; j++) { accS[pr][j] = 0ull; accN[pr][j] = 0ull; }

        __syncthreads();
        {   // A-tile load (rows are DH=128 wide)
            int node = base + m_ld;
            bool valid = node < NN;
            const float4* row = (const float4*)(A + (size_t)node * DH);
            #pragma unroll
            for (int i = 0; i < 16; i++) {
                int c = c0 + i * 4;
                float4 v = make_float4(0.f, 0.f, 0.f, 0.f);
                if (valid) v = row[c >> 2];
                As[(c + 0) * 128 + m_ld] = v.x;
                As[(c + 1) * 128 + m_ld] = v.y;
                As[(c + 2) * 128 + m_ld] = v.z;
                As[(c + 3) * 128 + m_ld] = v.w;
            }
        }
        __syncthreads();
        #pragma unroll 2
        for (int k = 0; k < 128; ++k) {
            ulonglong2 a0 = *(const ulonglong2*)(As + k * 128 + (ty << 3));
            ulonglong2 a1 = *(const ulonglong2*)(As + k * 128 + (ty << 3) + 4);
            float4 bs = *(const float4*)(Ws + k * NC + (tx << 2));
            float4 bn = *(const float4*)(Wn + k * NC + (tx << 2));
            unsigned long long ap[4] = {a0.x, a0.y, a1.x, a1.y};
            unsigned long long bsd[4] = {dup2(bs.x), dup2(bs.y), dup2(bs.z), dup2(bs.w)};
            unsigned long long bnd[4] = {dup2(bn.x), dup2(bn.y), dup2(bn.z), dup2(bn.w)};
            #pragma unroll
            for (int pr = 0; pr < 4; pr++) {
                #pragma unroll
                for (int j = 0; j < 4; j++) ffma2(accS[pr][j], ap[pr], bsd[j]);
                #pragma unroll
                for (int j = 0; j < 4; j++) ffma2(accN[pr][j], ap[pr], bnd[j]);
            }
        }
        // epilogue: self+bias -> out_ext ; neigh -> g_p
        #pragma unroll
        for (int pr = 0; pr < 4; pr++) {
            float2 vs[4], vn[4];
            #pragma unroll
            for (int j = 0; j < 4; j++) { vs[j] = unpk(accS[pr][j]); vn[j] = unpk(accN[pr][j]); }
            #pragma unroll
            for (int half = 0; half < 2; half++) {
                int r = base + (ty << 3) + pr * 2 + half;
                if (r < NN) {
                    float4 os, on;
                    os.x = (half ? vs[0].y : vs[0].x) + bb.x;
                    os.y = (half ? vs[1].y : vs[1].x) + bb.y;
                    os.z = (half ? vs[2].y : vs[2].x) + bb.z;
                    os.w = (half ? vs[3].y : vs[3].x) + bb.w;
                    on.x = half ? vn[0].y : vn[0].x;
                    on.y = half ? vn[1].y : vn[1].x;
                    on.z = half ? vn[2].y : vn[2].x;
                    on.w = half ? vn[3].y : vn[3].x;
                    *(float4*)(out_ext + (size_t)r * NC + (tx << 2)) = os;
                    *(float4*)(g_p     + (size_t)r * NC + (tx << 2)) = on;
                }
            }
        }
    }
}

// ---------------------------------------------------------------------------
// Final epilogue: out += nbr2 / max(deg,1)
// ---------------------------------------------------------------------------
__global__ void final_kernel(float* __restrict__ out) {
    int i = blockIdx.x * blockDim.x + threadIdx.x;   // float4 index
    if (i >= NN * (NC / 4)) return;
    int node = i >> 4;                               // 16 float4 per node
    float inv = 1.0f / fmaxf(g_deg[node], 1.0f);
    float4 nv = ((const float4*)g_nbr2)[i];
    float4 o = ((float4*)out)[i];
    o.x += nv.x * inv; o.y += nv.y * inv;
    o.z += nv.z * inv; o.w += nv.w * inv;
    ((float4*)out)[i] = o;
}

// ---------------------------------------------------------------------------
extern "C" void kernel_launch(void* const* d_in, const int* in_sizes, int n_in,
                              void* d_out, int out_size) {
    const float* x    = (const float*)d_in[0];
    const int*   src  = (const int*)d_in[1];
    const int*   dst  = (const int*)d_in[2];
    const float* Ws1  = (const float*)d_in[3];
    const float* Wn1  = (const float*)d_in[4];
    const float* b1   = (const float*)d_in[5];
    const float* Ws2  = (const float*)d_in[6];
    const float* Wn2  = (const float*)d_in[7];
    const float* b2   = (const float*)d_in[8];
    float* out = (float*)d_out;

    const int SMEM1 = (2 * DI * DH + 128 * 128) * 4;   // 192 KB
    const int SMEM2 = (2 * DH * NC + 128 * 128) * 4;   // 128 KB
    cudaFuncSetAttribute(gemm1_kernel,   cudaFuncAttributeMaxDynamicSharedMemorySize, SMEM1);
    cudaFuncSetAttribute(gemm64f_kernel, cudaFuncAttributeMaxDynamicSharedMemorySize, SMEM2);

    // 1) zero accumulators + degree
    {
        int total4 = NN * DI / 4 + NN * NC / 4 + NN / 4;
        zero_kernel<<<(total4 + 255) / 256, 256>>>();
    }
    // 2) layer-1 scatter (+ degree)
    scatter1_kernel<<<(NE * 32 + 255) / 256, 256>>>(x, src, dst);
    // 3) layer-1 fused GEMM -> g_h1
    gemm1_kernel<<<148, 256, SMEM1>>>(x, Ws1, Wn1, b1);
    // 4) fused dual GEMM: d_out = h1@Ws2 + b2 ; g_p = h1@Wn2
    gemm64f_kernel<<<148, 256, SMEM2>>>(Ws2, Wn2, b2, out);
    // 5) layer-2 scatter of g_p (64-wide, half-warp per edge)
    scatter2_kernel<<<(NE / 2 * 32 + 255) / 256, 256>>>(src, dst);
    // 6) out += nbr2 / deg
    final_kernel<<<(NN * (NC / 4) + 255) / 256, 256>>>(out);
}

// round 8
// speedup vs baseline: 1.2513x; 1.2513x over previous
#include <cuda_runtime.h>

#define NN 100000
#define NE 600000
#define DI 128
#define DH 128
#define NC 64

// Scratch (device globals -- referenced ONLY inside kernels, never from host)
__device__ __align__(16) float g_nbr1[(size_t)NN * DI];   // layer-1 neighbor sums (128-wide)
__device__ __align__(16) float g_h1[(size_t)NN * DH];     // layer-1 activations
__device__ __align__(16) float g_p[(size_t)NN * NC];      // h1 @ Wn2 (pre-projected, 64-wide)
__device__ __align__(16) float g_nbr2[(size_t)NN * NC];   // layer-2 neighbor sums (64-wide)
__device__ float g_deg[NN];                               // in-degree (float)

// ---------------- packed f32x2 helpers (sm_103a FFMA2) ----------------
__device__ __forceinline__ unsigned long long dup2(float x) {
    unsigned long long r;
    asm("mov.b64 %0, {%1, %1};" : "=l"(r) : "f"(x));
    return r;
}
__device__ __forceinline__ void ffma2(unsigned long long& d,
                                      unsigned long long a, unsigned long long b) {
    asm("fma.rn.f32x2 %0, %1, %2, %0;" : "+l"(d) : "l"(a), "l"(b));
}
__device__ __forceinline__ float2 unpk(unsigned long long v) {
    float2 f;
    asm("mov.b64 {%0, %1}, %2;" : "=f"(f.x), "=f"(f.y) : "l"(v));
    return f;
}

// ---------------------------------------------------------------------------
__global__ void zero_kernel() {
    const int n1 = NN * DI / 4;
    const int n2 = NN * NC / 4;
    const int nd = NN / 4;
    int i = blockIdx.x * blockDim.x + threadIdx.x;
    float4 z = make_float4(0.f, 0.f, 0.f, 0.f);
    if (i < n1)                 ((float4*)g_nbr1)[i] = z;
    else if (i < n1 + n2)       ((float4*)g_nbr2)[i - n1] = z;
    else if (i < n1 + n2 + nd)  ((float4*)g_deg)[i - n1 - n2] = z;
}

// ---------------------------------------------------------------------------
// Layer-1 edge scatter: warp per edge, 128 floats as 32 x float4 REDG, + degree
// ---------------------------------------------------------------------------
__global__ void scatter1_kernel(const float* __restrict__ x,
                                const int* __restrict__ src,
                                const int* __restrict__ dst) {
    int gw = (blockIdx.x * blockDim.x + threadIdx.x) >> 5;
    if (gw >= NE) return;
    int lane = threadIdx.x & 31;
    int s = __ldg(src + gw);
    int d = __ldg(dst + gw);
    float4 v = ((const float4*)x)[(size_t)s * 32 + lane];
    float4* p = ((float4*)g_nbr1) + (size_t)d * 32 + lane;
    asm volatile("red.global.add.v4.f32 [%0], {%1, %2, %3, %4};"
                 :: "l"(p), "f"(v.x), "f"(v.y), "f"(v.z), "f"(v.w)
                 : "memory");
    if (lane == 0) atomicAdd(&g_deg[d], 1.0f);
}

// ---------------------------------------------------------------------------
// Layer-2 edge scatter of pre-projected g_p (64-wide): HALF-warp per edge.
// ---------------------------------------------------------------------------
__global__ void scatter2_kernel(const int* __restrict__ src,
                                const int* __restrict__ dst) {
    int gw = (blockIdx.x * blockDim.x + threadIdx.x) >> 5;
    int lane = threadIdx.x & 31;
    int e = gw * 2 + (lane >> 4);
    if (e >= NE) return;
    int l16 = lane & 15;
    int s = __ldg(src + e);
    int d = __ldg(dst + e);
    float4 v = ((const float4*)g_p)[(size_t)s * 16 + l16];
    float4* p = ((float4*)g_nbr2) + (size_t)d * 16 + l16;
    asm volatile("red.global.add.v4.f32 [%0], {%1, %2, %3, %4};"
                 :: "l"(p), "f"(v.x), "f"(v.y), "f"(v.z), "f"(v.w)
                 : "memory");
}

// ---------------------------------------------------------------------------
// Layer 1: h1 = relu(x @ Wself + (nbr1/max(deg,1)) @ Wneigh + b1)
// M-tile 128, N=128, K=2x128 phases. 512 threads (16 warps), thread tile
// 4M(2 pairs)x8N = 16 FFMA2/k. SMEM: Ws 64K + Wn 64K + As 64K = 192KB.
// ---------------------------------------------------------------------------
__global__ void __launch_bounds__(512)
gemm1_kernel(const float* __restrict__ x,
             const float* __restrict__ Ws_g,
             const float* __restrict__ Wn_g,
             const float* __restrict__ bias) {
    extern __shared__ float sm[];
    float* Ws = sm;                 // [128][128]
    float* Wn = sm + DI * DH;       // [128][128]
    float* As = sm + 2 * DI * DH;   // [128 k][128 m]

    int tid = threadIdx.x;
    {
        const float4* s4 = (const float4*)Ws_g;
        const float4* n4 = (const float4*)Wn_g;
        float4* ws4 = (float4*)Ws;
        float4* wn4 = (float4*)Wn;
        for (int i = tid; i < DI * DH / 4; i += 512) { ws4[i] = s4[i]; wn4[i] = n4[i]; }
    }
    int ty = tid >> 4;              // 0..31 -> rows ty*4 (2 pairs)
    int tx = tid & 15;              // cols tx*8 .. +7
    float bb[8];
    #pragma unroll
    for (int j = 0; j < 8; j++) bb[j] = __ldg(bias + (tx << 3) + j);

    int m_ld = tid >> 2;            // 0..127: node row this thread loads
    int c0 = (tid & 3) * 32;        // feature quarter

    const int nTiles = (NN + 127) / 128;
    for (int tile = blockIdx.x; tile < nTiles; tile += gridDim.x) {
        int base = tile * 128;
        unsigned long long acc[2][8];
        #pragma unroll
        for (int pr = 0; pr < 2; pr++)
            #pragma unroll
            for (int j = 0; j < 8; j++) acc[pr][j] = 0ull;

        #pragma unroll
        for (int ph = 0; ph < 2; ++ph) {
            __syncthreads();
            {   // A-tile load: 128 nodes x 128 feats, K-major transposed
                const float* feat = ph ? g_nbr1 : x;
                int node = base + m_ld;
                bool valid = node < NN;
                float scale = 1.0f;
                if (ph && valid) scale = 1.0f / fmaxf(g_deg[node], 1.0f);
                const float4* row = (const float4*)(feat + (size_t)node * DI);
                #pragma unroll
                for (int i = 0; i < 8; i++) {
                    int c = c0 + i * 4;
                    float4 v = make_float4(0.f, 0.f, 0.f, 0.f);
                    if (valid) v = row[c >> 2];
                    As[(c + 0) * 128 + m_ld] = v.x * scale;
                    As[(c + 1) * 128 + m_ld] = v.y * scale;
                    As[(c + 2) * 128 + m_ld] = v.z * scale;
                    As[(c + 3) * 128 + m_ld] = v.w * scale;
                }
            }
            __syncthreads();
            const float* W = ph ? Wn : Ws;
            #pragma unroll 4
            for (int k = 0; k < 128; ++k) {
                ulonglong2 a = *(const ulonglong2*)(As + k * 128 + (ty << 2));
                float4 b0 = *(const float4*)(W + k * DH + (tx << 3));
                float4 b1 = *(const float4*)(W + k * DH + (tx << 3) + 4);
                unsigned long long ap[2] = {a.x, a.y};
                unsigned long long bd[8] = {dup2(b0.x), dup2(b0.y), dup2(b0.z), dup2(b0.w),
                                            dup2(b1.x), dup2(b1.y), dup2(b1.z), dup2(b1.w)};
                #pragma unroll
                for (int pr = 0; pr < 2; pr++)
                    #pragma unroll
                    for (int j = 0; j < 8; j++)
                        ffma2(acc[pr][j], ap[pr], bd[j]);
            }
        }
        // epilogue: bias + relu -> g_h1
        #pragma unroll
        for (int pr = 0; pr < 2; pr++) {
            float2 v[8];
            #pragma unroll
            for (int j = 0; j < 8; j++) v[j] = unpk(acc[pr][j]);
            #pragma unroll
            for (int half = 0; half < 2; half++) {
                int r = base + (ty << 2) + pr * 2 + half;
                if (r < NN) {
                    float* o = g_h1 + (size_t)r * DH + (tx << 3);
                    float e0 = half ? v[0].y : v[0].x;
                    float e1 = half ? v[1].y : v[1].x;
                    float e2 = half ? v[2].y : v[2].x;
                    float e3 = half ? v[3].y : v[3].x;
                    float e4 = half ? v[4].y : v[4].x;
                    float e5 = half ? v[5].y : v[5].x;
                    float e6 = half ? v[6].y : v[6].x;
                    float e7 = half ? v[7].y : v[7].x;
                    float4 o0, o1;
                    o0.x = fmaxf(e0 + bb[0], 0.f); o0.y = fmaxf(e1 + bb[1], 0.f);
                    o0.z = fmaxf(e2 + bb[2], 0.f); o0.w = fmaxf(e3 + bb[3], 0.f);
                    o1.x = fmaxf(e4 + bb[4], 0.f); o1.y = fmaxf(e5 + bb[5], 0.f);
                    o1.z = fmaxf(e6 + bb[6], 0.f); o1.w = fmaxf(e7 + bb[7], 0.f);
                    *(float4*)o = o0; *(float4*)(o + 4) = o1;
                }
            }
        }
    }
}

// ---------------------------------------------------------------------------
// Fused N=64 dual-GEMM: one pass over A = g_h1 computes BOTH
//   d_out = h1 @ Ws2 + b2   (nbr2/deg added by final_kernel)
//   g_p   = h1 @ Wn2
// M-tile 128, 512 threads (16 warps), thread tile 4M(2 pairs) x 4N x 2 mats
// = 16 FFMA2/k. SMEM: Ws 32K + Wn 32K + As 64K = 128KB.
// ---------------------------------------------------------------------------
__global__ void __launch_bounds__(512)
gemm64f_kernel(const float* __restrict__ Ws_g,
               const float* __restrict__ Wn_g,
               const float* __restrict__ bias,
               float* __restrict__ out_ext) {
    extern __shared__ float sm[];
    float* Ws = sm;                 // [128][64]
    float* Wn = sm + DH * NC;       // [128][64]
    float* As = sm + 2 * DH * NC;   // [128 k][128 m]

    const float* A = g_h1;

    int tid = threadIdx.x;
    {
        const float4* s4 = (const float4*)Ws_g;
        const float4* n4 = (const float4*)Wn_g;
        float4* ws4 = (float4*)Ws;
        float4* wn4 = (float4*)Wn;
        for (int i = tid; i < DH * NC / 4; i += 512) { ws4[i] = s4[i]; wn4[i] = n4[i]; }
    }
    int ty = tid >> 4;              // 0..31 -> rows ty*4 (2 pairs)
    int tx = tid & 15;              // cols tx*4
    float4 bb = *(const float4*)(bias + (tx << 2));

    int m_ld = tid >> 2;
    int c0 = (tid & 3) * 32;

    const int nTiles = (NN + 127) / 128;
    for (int tile = blockIdx.x; tile < nTiles; tile += gridDim.x) {
        int base = tile * 128;
        unsigned long long accS[2][4], accN[2][4];
        #pragma unroll
        for (int pr = 0; pr < 2; pr++)
            #pragma unroll
            for (int j = 0; j < 4; j++) { accS[pr][j] = 0ull; accN[pr][j] = 0ull; }

        __syncthreads();
        {   // A-tile load (rows are DH=128 wide)
            int node = base + m_ld;
            bool valid = node < NN;
            const float4* row = (const float4*)(A + (size_t)node * DH);
            #pragma unroll
            for (int i = 0; i < 8; i++) {
                int c = c0 + i * 4;
                float4 v = make_float4(0.f, 0.f, 0.f, 0.f);
                if (valid) v = row[c >> 2];
                As[(c + 0) * 128 + m_ld] = v.x;
                As[(c + 1) * 128 + m_ld] = v.y;
                As[(c + 2) * 128 + m_ld] = v.z;
                As[(c + 3) * 128 + m_ld] = v.w;
            }
        }
        __syncthreads();
        #pragma unroll 4
        for (int k = 0; k < 128; ++k) {
            ulonglong2 a = *(const ulonglong2*)(As + k * 128 + (ty << 2));
            float4 bs = *(const float4*)(Ws + k * NC + (tx << 2));
            float4 bn = *(const float4*)(Wn + k * NC + (tx << 2));
            unsigned long long ap[2] = {a.x, a.y};
            unsigned long long bsd[4] = {dup2(bs.x), dup2(bs.y), dup2(bs.z), dup2(bs.w)};
            unsigned long long bnd[4] = {dup2(bn.x), dup2(bn.y), dup2(bn.z), dup2(bn.w)};
            #pragma unroll
            for (int pr = 0; pr < 2; pr++) {
                #pragma unroll
                for (int j = 0; j < 4; j++) ffma2(accS[pr][j], ap[pr], bsd[j]);
                #pragma unroll
                for (int j = 0; j < 4; j++) ffma2(accN[pr][j], ap[pr], bnd[j]);
            }
        }
        // epilogue: self+bias -> out_ext ; neigh -> g_p
        #pragma unroll
        for (int pr = 0; pr < 2; pr++) {
            float2 vs[4], vn[4];
            #pragma unroll
            for (int j = 0; j < 4; j++) { vs[j] = unpk(accS[pr][j]); vn[j] = unpk(accN[pr][j]); }
            #pragma unroll
            for (int half = 0; half < 2; half++) {
                int r = base + (ty << 2) + pr * 2 + half;
                if (r < NN) {
                    float4 os, on;
                    os.x = (half ? vs[0].y : vs[0].x) + bb.x;
                    os.y = (half ? vs[1].y : vs[1].x) + bb.y;
                    os.z = (half ? vs[2].y : vs[2].x) + bb.z;
                    os.w = (half ? vs[3].y : vs[3].x) + bb.w;
                    on.x = half ? vn[0].y : vn[0].x;
                    on.y = half ? vn[1].y : vn[1].x;
                    on.z = half ? vn[2].y : vn[2].x;
                    on.w = half ? vn[3].y : vn[3].x;
                    *(float4*)(out_ext + (size_t)r * NC + (tx << 2)) = os;
                    *(float4*)(g_p     + (size_t)r * NC + (tx << 2)) = on;
                }
            }
        }
    }
}

// ---------------------------------------------------------------------------
// Final epilogue: out += nbr2 / max(deg,1)
// ---------------------------------------------------------------------------
__global__ void final_kernel(float* __restrict__ out) {
    int i = blockIdx.x * blockDim.x + threadIdx.x;   // float4 index
    if (i >= NN * (NC / 4)) return;
    int node = i >> 4;                               // 16 float4 per node
    float inv = 1.0f / fmaxf(g_deg[node], 1.0f);
    float4 nv = ((const float4*)g_nbr2)[i];
    float4 o = ((float4*)out)[i];
    o.x += nv.x * inv; o.y += nv.y * inv;
    o.z += nv.z * inv; o.w += nv.w * inv;
    ((float4*)out)[i] = o;
}

// ---------------------------------------------------------------------------
extern "C" void kernel_launch(void* const* d_in, const int* in_sizes, int n_in,
                              void* d_out, int out_size) {
    const float* x    = (const float*)d_in[0];
    const int*   src  = (const int*)d_in[1];
    const int*   dst  = (const int*)d_in[2];
    const float* Ws1  = (const float*)d_in[3];
    const float* Wn1  = (const float*)d_in[4];
    const float* b1   = (const float*)d_in[5];
    const float* Ws2  = (const float*)d_in[6];
    const float* Wn2  = (const float*)d_in[7];
    const float* b2   = (const float*)d_in[8];
    float* out = (float*)d_out;

    const int SMEM1 = (2 * DI * DH + 128 * 128) * 4;   // 192 KB
    const int SMEM2 = (2 * DH * NC + 128 * 128) * 4;   // 128 KB
    cudaFuncSetAttribute(gemm1_kernel,   cudaFuncAttributeMaxDynamicSharedMemorySize, SMEM1);
    cudaFuncSetAttribute(gemm64f_kernel, cudaFuncAttributeMaxDynamicSharedMemorySize, SMEM2);

    // 1) zero accumulators + degree
    {
        int total4 = NN * DI / 4 + NN * NC / 4 + NN / 4;
        zero_kernel<<<(total4 + 255) / 256, 256>>>();
    }
    // 2) layer-1 scatter (+ degree)
    scatter1_kernel<<<(NE * 32 + 255) / 256, 256>>>(x, src, dst);
    // 3) layer-1 fused GEMM -> g_h1
    gemm1_kernel<<<148, 512, SMEM1>>>(x, Ws1, Wn1, b1);
    // 4) fused dual GEMM: d_out = h1@Ws2 + b2 ; g_p = h1@Wn2
    gemm64f_kernel<<<148, 512, SMEM2>>>(Ws2, Wn2, b2, out);
    // 5) layer-2 scatter of g_p (64-wide, half-warp per edge)
    scatter2_kernel<<<(NE / 2 * 32 + 255) / 256, 256>>>(src, dst);
    // 6) out += nbr2 / deg
    final_kernel<<<(NN * (NC / 4) + 255) / 256, 256>>>(out);
}

// round 11
// speedup vs baseline: 1.7977x; 1.4366x over previous
#include <cuda_runtime.h>
#include <cuda_bf16.h>
#include <cstdint>
#include <stdint.h>

#define NN 100000
#define NE 600000
#define DI 128
#define DH 128
#define NC 64

// Scratch (device globals -- referenced ONLY inside kernels, never from host)
__device__ __align__(16) float g_nbr1[(size_t)NN * DI];   // layer-1 neighbor sums
__device__ __align__(16) float g_h1[(size_t)NN * DH];     // layer-1 activations (fp32)
__device__ __align__(16) float g_p[(size_t)NN * NC];      // h1 @ Wn2 (pre-projected)
__device__ __align__(16) float g_nbr2[(size_t)NN * NC];   // layer-2 neighbor sums
__device__ float g_deg[NN];                               // in-degree (float)
// Pre-converted layer-1 weights, B[n][k] = W[k][n], bf16 hi/lo, [ph][128n][128k]
__device__ __align__(16) __nv_bfloat16 g_B1hi[2 * 128 * 128];
__device__ __align__(16) __nv_bfloat16 g_B1lo[2 * 128 * 128];

// ---------------- packed f32x2 helpers (sm_103a FFMA2) ----------------
__device__ __forceinline__ unsigned long long dup2(float x) {
    unsigned long long r;
    asm("mov.b64 %0, {%1, %1};" : "=l"(r) : "f"(x));
    return r;
}
__device__ __forceinline__ void ffma2(unsigned long long& d,
                                      unsigned long long a, unsigned long long b) {
    asm("fma.rn.f32x2 %0, %1, %2, %0;" : "+l"(d) : "l"(a), "l"(b));
}
__device__ __forceinline__ float2 unpk(unsigned long long v) {
    float2 f;
    asm("mov.b64 {%0, %1}, %2;" : "=f"(f.x), "=f"(f.y) : "l"(v));
    return f;
}

// ---------------- HMMA helpers (baseline PTX, sm_80+, no 'a' target) ----
__device__ __forceinline__ uint32_t smem_to_u32(const void* p) {
    uint32_t a;
    asm("{ .reg .u64 t; cvta.to.shared.u64 t, %1; cvt.u32.u64 %0, t; }" : "=r"(a) : "l"(p));
    return a;
}
__device__ __forceinline__ void ldsm_x4(uint32_t* r, uint32_t addr) {
    asm volatile("ldmatrix.sync.aligned.m8n8.x4.shared.b16 {%0,%1,%2,%3}, [%4];"
                 : "=r"(r[0]), "=r"(r[1]), "=r"(r[2]), "=r"(r[3]) : "r"(addr));
}
__device__ __forceinline__ void mma_bf16(float* d, const uint32_t* a, const uint32_t* b) {
    asm volatile("mma.sync.aligned.m16n8k16.row.col.f32.bf16.bf16.f32 "
                 "{%0,%1,%2,%3}, {%4,%5,%6,%7}, {%8,%9}, {%0,%1,%2,%3};"
                 : "+f"(d[0]), "+f"(d[1]), "+f"(d[2]), "+f"(d[3])
                 : "r"(a[0]), "r"(a[1]), "r"(a[2]), "r"(a[3]), "r"(b[0]), "r"(b[1]));
}

// SMEM map for gemm1_mma: rows padded to 136 bf16 (272B) -> conflict-free ldsm
#define RSTR 272
#define TILE_B (128 * RSTR)        // 34816 bytes per 128x128 bf16 tile
#define SM_A_HI 0
#define SM_A_LO TILE_B
#define SM_B    (2 * TILE_B)       // 4 tiles: [ph][hi/lo]
#define SMEM_MMA (6 * TILE_B)      // 208896 B

// ---------------------------------------------------------------------------
__global__ void zero_kernel() {
    const int n1 = NN * DI / 4;
    const int n2 = NN * NC / 4;
    const int nd = NN / 4;
    int i = blockIdx.x * blockDim.x + threadIdx.x;
    float4 z = make_float4(0.f, 0.f, 0.f, 0.f);
    if (i < n1)                 ((float4*)g_nbr1)[i] = z;
    else if (i < n1 + n2)       ((float4*)g_nbr2)[i - n1] = z;
    else if (i < n1 + n2 + nd)  ((float4*)g_deg)[i - n1 - n2] = z;
}

// ---------------------------------------------------------------------------
// Pre-convert layer-1 weights to transposed bf16 hi/lo: B[ph][n][k] = W_ph[k][n]
// ---------------------------------------------------------------------------
__global__ void convert_w1_kernel(const float* __restrict__ Ws1,
                                  const float* __restrict__ Wn1) {
    int i = blockIdx.x * blockDim.x + threadIdx.x;
    if (i >= 2 * 128 * 128) return;
    int ph = i >> 14, rem = i & 16383;
    int n = rem >> 7, k = rem & 127;
    const float* W = ph ? Wn1 : Ws1;
    float v = W[k * 128 + n];
    __nv_bfloat16 h = __float2bfloat16(v);
    __nv_bfloat16 l = __float2bfloat16(v - __bfloat162float(h));
    g_B1hi[i] = h;
    g_B1lo[i] = l;
}

// ---------------------------------------------------------------------------
// Layer-1 edge scatter (proven): warp per edge, REDG.128 x32 + degree
// ---------------------------------------------------------------------------
__global__ void scatter1_kernel(const float* __restrict__ x,
                                const int* __restrict__ src,
                                const int* __restrict__ dst) {
    int gw = (blockIdx.x * blockDim.x + threadIdx.x) >> 5;
    if (gw >= NE) return;
    int lane = threadIdx.x & 31;
    int s = __ldg(src + gw);
    int d = __ldg(dst + gw);
    float4 v = ((const float4*)x)[(size_t)s * 32 + lane];
    float4* p = ((float4*)g_nbr1) + (size_t)d * 32 + lane;
    asm volatile("red.global.add.v4.f32 [%0], {%1, %2, %3, %4};"
                 :: "l"(p), "f"(v.x), "f"(v.y), "f"(v.z), "f"(v.w)
                 : "memory");
    if (lane == 0) atomicAdd(&g_deg[d], 1.0f);
}

// ---------------------------------------------------------------------------
// Layer-2 edge scatter of g_p (64-wide): HALF-warp per edge (proven)
// ---------------------------------------------------------------------------
__global__ void scatter2_kernel(const int* __restrict__ src,
                                const int* __restrict__ dst) {
    int gw = (blockIdx.x * blockDim.x + threadIdx.x) >> 5;
    int lane = threadIdx.x & 31;
    int e = gw * 2 + (lane >> 4);
    if (e >= NE) return;
    int l16 = lane & 15;
    int s = __ldg(src + e);
    int d = __ldg(dst + e);
    float4 v = ((const float4*)g_p)[(size_t)s * 16 + l16];
    float4* p = ((float4*)g_nbr2) + (size_t)d * 16 + l16;
    asm volatile("red.global.add.v4.f32 [%0], {%1, %2, %3, %4};"
                 :: "l"(p), "f"(v.x), "f"(v.y), "f"(v.z), "f"(v.w)
                 : "memory");
}

// ---------------------------------------------------------------------------
// Layer 1 via HMMA (mma.sync bf16-split):
//   h1 = relu(x @ Ws1 + (nbr1/max(deg,1)) @ Wn1 + b1)
// M-tile 128, N=128, K=2 phases x 128. 256 threads = 8 warps (4 M x 2 N).
// Split: D += Ahi*Bhi + Ahi*Blo + Alo*Bhi, fp32 accum.
// A [m][k], B [n][k] in SMEM, 272B row stride, canonical ldmatrix fragments.
// ---------------------------------------------------------------------------
__global__ void __launch_bounds__(256)
gemm1_mma_kernel(const float* __restrict__ x,
                 const float* __restrict__ bias) {
    extern __shared__ char smem[];
    uint32_t smem_base = smem_to_u32(smem);
    int tid = threadIdx.x;
    int w = tid >> 5, l = tid & 31;
    int wm = w & 3, wn = w >> 2;

    // Preload all B tiles ([ph][hi/lo][128n][k], padded rows)
    {
        const uint32_t* hi32 = (const uint32_t*)g_B1hi;
        const uint32_t* lo32 = (const uint32_t*)g_B1lo;
        for (int i = tid; i < 32768; i += 256) {
            int kp = i & 63, n = (i >> 6) & 127, hilo = (i >> 13) & 1, ph = i >> 14;
            uint32_t v = (hilo ? lo32 : hi32)[ph * 8192 + n * 64 + kp];
            *(uint32_t*)(smem + SM_B + (ph * 2 + hilo) * TILE_B + n * RSTR + kp * 4) = v;
        }
    }

    int rowc = tid >> 1;               // A-convert row (0..127)
    int khalf = (tid & 1) << 6;        // feature half

    const int nTiles = (NN + 127) / 128;
    for (int tile = blockIdx.x; tile < nTiles; tile += gridDim.x) {
        int base = tile * 128;
        float acc[2][8][4];
        #pragma unroll
        for (int bm = 0; bm < 2; bm++)
            #pragma unroll
            for (int bn = 0; bn < 8; bn++)
                #pragma unroll
                for (int j = 0; j < 4; j++) acc[bm][bn][j] = 0.f;

        #pragma unroll
        for (int ph = 0; ph < 2; ++ph) {
            __syncthreads();   // prior ldmatrix reads of A done (or B preload, tile 0)
            {   // convert A tile: fp32 -> bf16 hi/lo rows [m][k]
                const float* feat = ph ? g_nbr1 : x;
                int node = base + rowc;
                bool valid = node < NN;
                float scale = 1.0f;
                if (ph && valid) scale = 1.0f / fmaxf(g_deg[node], 1.0f);
                const float4* rp = (const float4*)(feat + (size_t)node * DI + khalf);
                #pragma unroll
                for (int i = 0; i < 16; i++) {
                    float4 v = make_float4(0.f, 0.f, 0.f, 0.f);
                    if (valid) v = rp[i];
                    v.x *= scale; v.y *= scale; v.z *= scale; v.w *= scale;
                    int c = khalf + i * 4;
                    __nv_bfloat162 h01, l01, h23, l23;
                    h01.x = __float2bfloat16(v.x);
                    l01.x = __float2bfloat16(v.x - __bfloat162float(h01.x));
                    h01.y = __float2bfloat16(v.y);
                    l01.y = __float2bfloat16(v.y - __bfloat162float(h01.y));
                    h23.x = __float2bfloat16(v.z);
                    l23.x = __float2bfloat16(v.z - __bfloat162float(h23.x));
                    h23.y = __float2bfloat16(v.w);
                    l23.y = __float2bfloat16(v.w - __bfloat162float(h23.y));
                    uint32_t o = (uint32_t)(rowc * RSTR + c * 2);
                    *(__nv_bfloat162*)(smem + SM_A_HI + o)     = h01;
                    *(__nv_bfloat162*)(smem + SM_A_HI + o + 4) = h23;
                    *(__nv_bfloat162*)(smem + SM_A_LO + o)     = l01;
                    *(__nv_bfloat162*)(smem + SM_A_LO + o + 4) = l23;
                }
            }
            __syncthreads();

            uint32_t bb_hi = smem_base + SM_B + (uint32_t)(ph * 2) * TILE_B;
            #pragma unroll
            for (int s = 0; s < 8; s++) {
                int k0 = s << 4;
                // A fragments: blocks (m0-7,k0-7),(m8-15,k0-7),(m0-7,k8-15),(m8-15,k8-15)
                uint32_t ahi[2][4], alo[2][4];
                #pragma unroll
                for (int bm = 0; bm < 2; bm++) {
                    int row = (wm << 5) + (bm << 4) + (l & 7) + (((l >> 3) & 1) << 3);
                    int col = k0 + ((l >> 4) << 3);
                    uint32_t ad = smem_base + (uint32_t)(row * RSTR + col * 2);
                    ldsm_x4(ahi[bm], ad + SM_A_HI);
                    ldsm_x4(alo[bm], ad + SM_A_LO);
                }
                // B fragments: x4 = 2 n8-tiles x 2 k-halves
                uint32_t bhi[8][2], blo[8][2];
                #pragma unroll
                for (int t = 0; t < 4; t++) {
                    int row = (wn << 6) + (t << 4) + (l & 7) + ((l >> 4) << 3);
                    int col = k0 + (((l >> 3) & 1) << 3);
                    uint32_t bd = bb_hi + (uint32_t)(row * RSTR + col * 2);
                    uint32_t r[4];
                    ldsm_x4(r, bd);
                    bhi[2 * t][0] = r[0]; bhi[2 * t][1] = r[1];
                    bhi[2 * t + 1][0] = r[2]; bhi[2 * t + 1][1] = r[3];
                    ldsm_x4(r, bd + TILE_B);   // lo tile is +1 tile after hi
                    blo[2 * t][0] = r[0]; blo[2 * t][1] = r[1];
                    blo[2 * t + 1][0] = r[2]; blo[2 * t + 1][1] = r[3];
                }
                #pragma unroll
                for (int bm = 0; bm < 2; bm++)
                    #pragma unroll
                    for (int bn = 0; bn < 8; bn++) {
                        mma_bf16(acc[bm][bn], ahi[bm], bhi[bn]);
                        mma_bf16(acc[bm][bn], ahi[bm], blo[bn]);
                        mma_bf16(acc[bm][bn], alo[bm], bhi[bn]);
                    }
            }
        }

        // Epilogue: bias + relu -> g_h1 (fragment D layout: c0/c1 row=l/4, c2/c3 row+8)
        #pragma unroll
        for (int bm = 0; bm < 2; bm++) {
            int r0 = base + (wm << 5) + (bm << 4) + (l >> 2);
            #pragma unroll
            for (int bn = 0; bn < 8; bn++) {
                int n = (wn << 6) + (bn << 3) + ((l & 3) << 1);
                float2 bv = *(const float2*)(bias + n);
                if (r0 < NN) {
                    float2 o;
                    o.x = fmaxf(acc[bm][bn][0] + bv.x, 0.f);
                    o.y = fmaxf(acc[bm][bn][1] + bv.y, 0.f);
                    *(float2*)(g_h1 + (size_t)r0 * DH + n) = o;
                }
                if (r0 + 8 < NN) {
                    float2 o;
                    o.x = fmaxf(acc[bm][bn][2] + bv.x, 0.f);
                    o.y = fmaxf(acc[bm][bn][3] + bv.y, 0.f);
                    *(float2*)(g_h1 + (size_t)(r0 + 8) * DH + n) = o;
                }
            }
        }
    }
}

// ---------------------------------------------------------------------------
// Fused N=64 dual-GEMM (proven R8 FFMA2): one pass over g_h1 computes
//   d_out = h1 @ Ws2 + b2 ; g_p = h1 @ Wn2
// ---------------------------------------------------------------------------
__global__ void __launch_bounds__(512)
gemm64f_kernel(const float* __restrict__ Ws_g,
               const float* __restrict__ Wn_g,
               const float* __restrict__ bias,
               float* __restrict__ out_ext) {
    extern __shared__ float sm[];
    float* Ws = sm;                 // [128][64]
    float* Wn = sm + DH * NC;       // [128][64]
    float* As = sm + 2 * DH * NC;   // [128 k][128 m]

    const float* A = g_h1;

    int tid = threadIdx.x;
    {
        const float4* s4 = (const float4*)Ws_g;
        const float4* n4 = (const float4*)Wn_g;
        float4* ws4 = (float4*)Ws;
        float4* wn4 = (float4*)Wn;
        for (int i = tid; i < DH * NC / 4; i += 512) { ws4[i] = s4[i]; wn4[i] = n4[i]; }
    }
    int ty = tid >> 4;              // 0..31 -> rows ty*4 (2 pairs)
    int tx = tid & 15;              // cols tx*4
    float4 bb = *(const float4*)(bias + (tx << 2));

    int m_ld = tid >> 2;
    int c0 = (tid & 3) * 32;

    const int nTiles = (NN + 127) / 128;
    for (int tile = blockIdx.x; tile < nTiles; tile += gridDim.x) {
        int base = tile * 128;
        unsigned long long accS[2][4], accN[2][4];
        #pragma unroll
        for (int pr = 0; pr < 2; pr++)
            #pragma unroll
            for (int j = 0; j < 4; j++) { accS[pr][j] = 0ull; accN[pr][j] = 0ull; }

        __syncthreads();
        {
            int node = base + m_ld;
            bool valid = node < NN;
            const float4* row = (const float4*)(A + (size_t)node * DH);
            #pragma unroll
            for (int i = 0; i < 8; i++) {
                int c = c0 + i * 4;
                float4 v = make_float4(0.f, 0.f, 0.f, 0.f);
                if (valid) v = row[c >> 2];
                As[(c + 0) * 128 + m_ld] = v.x;
                As[(c + 1) * 128 + m_ld] = v.y;
                As[(c + 2) * 128 + m_ld] = v.z;
                As[(c + 3) * 128 + m_ld] = v.w;
            }
        }
        __syncthreads();
        #pragma unroll 4
        for (int k = 0; k < 128; ++k) {
            ulonglong2 a = *(const ulonglong2*)(As + k * 128 + (ty << 2));
            float4 bs = *(const float4*)(Ws + k * NC + (tx << 2));
            float4 bn = *(const float4*)(Wn + k * NC + (tx << 2));
            unsigned long long ap[2] = {a.x, a.y};
            unsigned long long bsd[4] = {dup2(bs.x), dup2(bs.y), dup2(bs.z), dup2(bs.w)};
            unsigned long long bnd[4] = {dup2(bn.x), dup2(bn.y), dup2(bn.z), dup2(bn.w)};
            #pragma unroll
            for (int pr = 0; pr < 2; pr++) {
                #pragma unroll
                for (int j = 0; j < 4; j++) ffma2(accS[pr][j], ap[pr], bsd[j]);
                #pragma unroll
                for (int j = 0; j < 4; j++) ffma2(accN[pr][j], ap[pr], bnd[j]);
            }
        }
        #pragma unroll
        for (int pr = 0; pr < 2; pr++) {
            float2 vs[4], vn[4];
            #pragma unroll
            for (int j = 0; j < 4; j++) { vs[j] = unpk(accS[pr][j]); vn[j] = unpk(accN[pr][j]); }
            #pragma unroll
            for (int half = 0; half < 2; half++) {
                int r = base + (ty << 2) + pr * 2 + half;
                if (r < NN) {
                    float4 os, on;
                    os.x = (half ? vs[0].y : vs[0].x) + bb.x;
                    os.y = (half ? vs[1].y : vs[1].x) + bb.y;
                    os.z = (half ? vs[2].y : vs[2].x) + bb.z;
                    os.w = (half ? vs[3].y : vs[3].x) + bb.w;
                    on.x = half ? vn[0].y : vn[0].x;
                    on.y = half ? vn[1].y : vn[1].x;
                    on.z = half ? vn[2].y : vn[2].x;
                    on.w = half ? vn[3].y : vn[3].x;
                    *(float4*)(out_ext + (size_t)r * NC + (tx << 2)) = os;
                    *(float4*)(g_p     + (size_t)r * NC + (tx << 2)) = on;
                }
            }
        }
    }
}

// ---------------------------------------------------------------------------
__global__ void final_kernel(float* __restrict__ out) {
    int i = blockIdx.x * blockDim.x + threadIdx.x;
    if (i >= NN * (NC / 4)) return;
    int node = i >> 4;
    float inv = 1.0f / fmaxf(g_deg[node], 1.0f);
    float4 nv = ((const float4*)g_nbr2)[i];
    float4 o = ((float4*)out)[i];
    o.x += nv.x * inv; o.y += nv.y * inv;
    o.z += nv.z * inv; o.w += nv.w * inv;
    ((float4*)out)[i] = o;
}

// ---------------------------------------------------------------------------
extern "C" void kernel_launch(void* const* d_in, const int* in_sizes, int n_in,
                              void* d_out, int out_size) {
    const float* x    = (const float*)d_in[0];
    const int*   src  = (const int*)d_in[1];
    const int*   dst  = (const int*)d_in[2];
    const float* Ws1  = (const float*)d_in[3];
    const float* Wn1  = (const float*)d_in[4];
    const float* b1   = (const float*)d_in[5];
    const float* Ws2  = (const float*)d_in[6];
    const float* Wn2  = (const float*)d_in[7];
    const float* b2   = (const float*)d_in[8];
    float* out = (float*)d_out;

    const int SMEM2 = (2 * DH * NC + 128 * 128) * 4;   // 128 KB
    cudaFuncSetAttribute(gemm1_mma_kernel, cudaFuncAttributeMaxDynamicSharedMemorySize, SMEM_MMA);
    cudaFuncSetAttribute(gemm64f_kernel,   cudaFuncAttributeMaxDynamicSharedMemorySize, SMEM2);

    // 1) zero accumulators + degree; pre-convert W1 (independent)
    {
        int total4 = NN * DI / 4 + NN * NC / 4 + NN / 4;
        zero_kernel<<<(total4 + 255) / 256, 256>>>();
    }
    convert_w1_kernel<<<(2 * 128 * 128 + 255) / 256, 256>>>(Ws1, Wn1);
    // 2) layer-1 scatter (+ degree)
    scatter1_kernel<<<(NE * 32 + 255) / 256, 256>>>(x, src, dst);
    // 3) layer-1 GEMM on tensor cores (HMMA) -> g_h1 (fp32)
    gemm1_mma_kernel<<<148, 256, SMEM_MMA>>>(x, b1);
    // 4) fused dual GEMM: d_out = h1@Ws2 + b2 ; g_p = h1@Wn2
    gemm64f_kernel<<<148, 512, SMEM2>>>(Ws2, Wn2, b2, out);
    // 5) layer-2 scatter of g_p
    scatter2_kernel<<<(NE / 2 * 32 + 255) / 256, 256>>>(src, dst);
    // 6) out += nbr2 / deg
    final_kernel<<<(NN * (NC / 4) + 255) / 256, 256>>>(out);
}